// round 6
// baseline (speedup 1.0000x reference)
#include <cuda_runtime.h>
#include <math_constants.h>

// Problem constants (fixed by the dataset)
#define NN   20000      // nodes
#define EE   640000     // edges
#define HCC  128        // H * C
#define NH   4          // heads
#define CH   32         // channels per head
#define DOUT 64

// ---------------- device scratch (static: no allocations allowed) -----------
__device__ float g_XL[NN * HCC];
__device__ float g_XR[NN * HCC];
__device__ float g_H [NN * HCC];
__device__ int   g_cnt[NN];
__device__ int   g_cur[NN];
__device__ float g_asum[NN];     // sum of non-self incoming edge_attr
__device__ int   g_ascnt[NN];    // count of non-self incoming edges
__device__ int   g_rowptr[NN + 1];
__device__ int2  g_ecsr[EE];     // packed (src, edge_attr bits), CSR order by dst

// ---------------- CSR build ------------------------------------------------
__global__ void zero_counts_kernel() {
    int i = blockIdx.x * blockDim.x + threadIdx.x;
    if (i < NN) { g_cnt[i] = 0; g_cur[i] = 0; g_asum[i] = 0.f; g_ascnt[i] = 0; }
}

// histogram + per-dst non-self edge_attr sum/count (for fill_value='mean')
__global__ void hist_kernel(const int* __restrict__ ei,
                            const float* __restrict__ eattr, int E) {
    int e = blockIdx.x * blockDim.x + threadIdx.x;
    if (e >= E) return;
    int s = ei[e];
    int d = ei[E + e];
    if (d < 0 || d >= NN) return;
    atomicAdd(&g_cnt[d], 1);
    if (s != d) {
        atomicAdd(&g_asum[d], eattr[e]);
        atomicAdd(&g_ascnt[d], 1);
    }
}

// single-block exclusive scan of g_cnt -> g_rowptr
__global__ void scan_kernel(int n) {
    __shared__ int sums[1024];
    int tid = threadIdx.x;
    int per = (n + 1023) >> 10;
    int beg = tid * per;
    int end = beg + per;
    if (beg > n) beg = n;
    if (end > n) end = n;
    int s = 0;
    for (int i = beg; i < end; ++i) s += g_cnt[i];
    sums[tid] = s;
    __syncthreads();
    for (int off = 1; off < 1024; off <<= 1) {
        int v = (tid >= off) ? sums[tid - off] : 0;
        __syncthreads();
        sums[tid] += v;
        __syncthreads();
    }
    int run = (tid == 0) ? 0 : sums[tid - 1];
    for (int i = beg; i < end; ++i) { g_rowptr[i] = run; run += g_cnt[i]; }
    if (tid == 0) g_rowptr[n] = sums[1023];
}

__global__ void scatter_kernel(const int* __restrict__ ei,
                               const float* __restrict__ eattr, int E) {
    int e = blockIdx.x * blockDim.x + threadIdx.x;
    if (e >= E) return;
    int dst = ei[E + e];
    if (dst < 0 || dst >= NN) return;
    int pos = g_rowptr[dst] + atomicAdd(&g_cur[dst], 1);
    g_ecsr[pos] = make_int2(ei[e], __float_as_int(eattr[e]));
}

// ---------------- fused dual SGEMM: CL = A@Bl + bl, CR = A@Br + br ---------
// 64(M)x128(N) block tile, BK=16, 128 threads, 8x8 micro-tile per output.
// N == K == 128 fixed.
__global__ __launch_bounds__(128)
void sgemm_dual_bias(const float* __restrict__ A,
                     const float* __restrict__ Bl, const float* __restrict__ Br,
                     const float* __restrict__ bl, const float* __restrict__ br,
                     float* __restrict__ CL, float* __restrict__ CR,
                     int M) {
    __shared__ float As [16][64];   // transposed: As[k][m]
    __shared__ float Bls[16][128];  // Bls[k][n]
    __shared__ float Brs[16][128];
    int tid = threadIdx.x;
    int tx = tid & 15;              // col group 0..15 -> cols tx*8..+8
    int ty = tid >> 4;              // row group 0..7  -> rows ty*8..+8
    int rowBase = blockIdx.x * 64;

    float accL[8][8] = {};
    float accR[8][8] = {};

    for (int k0 = 0; k0 < 128; k0 += 16) {
        // A tile: 64 rows x 16 k = 256 float4, 2 per thread
        #pragma unroll
        for (int i = 0; i < 2; ++i) {
            int idx = tid * 2 + i;          // 0..255
            int r   = idx >> 2;             // 0..63
            int kq  = (idx & 3) * 4;        // 0,4,8,12
            int gr  = rowBase + r;
            float4 av = (gr < M) ? *(const float4*)&A[(long)gr * 128 + k0 + kq]
                                 : make_float4(0.f, 0.f, 0.f, 0.f);
            As[kq + 0][r] = av.x;
            As[kq + 1][r] = av.y;
            As[kq + 2][r] = av.z;
            As[kq + 3][r] = av.w;
        }
        // B tiles: 16 k x 128 n = 512 float4 each, 4 per thread
        #pragma unroll
        for (int i = 0; i < 4; ++i) {
            int idx = i * 128 + tid;        // 0..511
            int kr  = idx >> 5;             // 0..15
            int nc  = (idx & 31) * 4;       // 0..124
            long boff = (long)(k0 + kr) * 128 + nc;
            *(float4*)&Bls[kr][nc] = *(const float4*)&Bl[boff];
            *(float4*)&Brs[kr][nc] = *(const float4*)&Br[boff];
        }
        __syncthreads();
        #pragma unroll
        for (int kk = 0; kk < 16; ++kk) {
            float a[8], blv[8], brv[8];
            *(float4*)&a[0]   = *(const float4*)&As [kk][ty * 8];
            *(float4*)&a[4]   = *(const float4*)&As [kk][ty * 8 + 4];
            *(float4*)&blv[0] = *(const float4*)&Bls[kk][tx * 8];
            *(float4*)&blv[4] = *(const float4*)&Bls[kk][tx * 8 + 4];
            *(float4*)&brv[0] = *(const float4*)&Brs[kk][tx * 8];
            *(float4*)&brv[4] = *(const float4*)&Brs[kk][tx * 8 + 4];
            #pragma unroll
            for (int i = 0; i < 8; ++i)
                #pragma unroll
                for (int j = 0; j < 8; ++j) {
                    accL[i][j] = fmaf(a[i], blv[j], accL[i][j]);
                    accR[i][j] = fmaf(a[i], brv[j], accR[i][j]);
                }
        }
        __syncthreads();
    }

    float blb[8], brb[8];
    *(float4*)&blb[0] = *(const float4*)&bl[tx * 8];
    *(float4*)&blb[4] = *(const float4*)&bl[tx * 8 + 4];
    *(float4*)&brb[0] = *(const float4*)&br[tx * 8];
    *(float4*)&brb[4] = *(const float4*)&br[tx * 8 + 4];
    #pragma unroll
    for (int i = 0; i < 8; ++i) {
        int gr = rowBase + ty * 8 + i;
        if (gr < M) {
            long coff = (long)gr * 128 + tx * 8;
            float4 o0, o1, p0, p1;
            o0.x = accL[i][0] + blb[0]; o0.y = accL[i][1] + blb[1];
            o0.z = accL[i][2] + blb[2]; o0.w = accL[i][3] + blb[3];
            o1.x = accL[i][4] + blb[4]; o1.y = accL[i][5] + blb[5];
            o1.z = accL[i][6] + blb[6]; o1.w = accL[i][7] + blb[7];
            p0.x = accR[i][0] + brb[0]; p0.y = accR[i][1] + brb[1];
            p0.z = accR[i][2] + brb[2]; p0.w = accR[i][3] + brb[3];
            p1.x = accR[i][4] + brb[4]; p1.y = accR[i][5] + brb[5];
            p1.z = accR[i][6] + brb[6]; p1.w = accR[i][7] + brb[7];
            *(float4*)&CL[coff]     = o0;
            *(float4*)&CL[coff + 4] = o1;
            *(float4*)&CR[coff]     = p0;
            *(float4*)&CR[coff + 4] = p1;
        }
    }
}

// ---------------- output projection: C[M,64] = A[M,128] @ B[128,64] + bias --
// 128(M)x64(N) block tile, BK=16, 128 threads, 8x8 micro-tile.
__global__ __launch_bounds__(128)
void sgemm_out_bias(const float* __restrict__ A, const float* __restrict__ B,
                    const float* __restrict__ bias, float* __restrict__ C,
                    int M) {
    __shared__ float As[16][128];   // transposed: As[k][m]
    __shared__ float Bs[16][64];    // Bs[k][n]
    int tid = threadIdx.x;
    int tx = tid & 7;               // col group 0..7  -> cols tx*8..+8
    int ty = tid >> 3;              // row group 0..15 -> rows ty*8..+8
    int rowBase = blockIdx.x * 128;

    float acc[8][8] = {};

    for (int k0 = 0; k0 < 128; k0 += 16) {
        // A tile: 128 rows x 16 k = 512 float4, 4 per thread
        #pragma unroll
        for (int i = 0; i < 4; ++i) {
            int idx = tid * 4 + i;          // 0..511
            int r   = idx >> 2;             // 0..127
            int kq  = (idx & 3) * 4;
            int gr  = rowBase + r;
            float4 av = (gr < M) ? *(const float4*)&A[(long)gr * 128 + k0 + kq]
                                 : make_float4(0.f, 0.f, 0.f, 0.f);
            As[kq + 0][r] = av.x;
            As[kq + 1][r] = av.y;
            As[kq + 2][r] = av.z;
            As[kq + 3][r] = av.w;
        }
        // B tile: 16 k x 64 n = 256 float4, 2 per thread
        #pragma unroll
        for (int i = 0; i < 2; ++i) {
            int idx = i * 128 + tid;        // 0..255
            int kr  = idx >> 4;             // 0..15
            int nc  = (idx & 15) * 4;       // 0..60
            *(float4*)&Bs[kr][nc] = *(const float4*)&B[(long)(k0 + kr) * 64 + nc];
        }
        __syncthreads();
        #pragma unroll
        for (int kk = 0; kk < 16; ++kk) {
            float a[8], b[8];
            *(float4*)&a[0] = *(const float4*)&As[kk][ty * 8];
            *(float4*)&a[4] = *(const float4*)&As[kk][ty * 8 + 4];
            *(float4*)&b[0] = *(const float4*)&Bs[kk][tx * 8];
            *(float4*)&b[4] = *(const float4*)&Bs[kk][tx * 8 + 4];
            #pragma unroll
            for (int i = 0; i < 8; ++i)
                #pragma unroll
                for (int j = 0; j < 8; ++j)
                    acc[i][j] = fmaf(a[i], b[j], acc[i][j]);
        }
        __syncthreads();
    }

    float bb[8];
    *(float4*)&bb[0] = *(const float4*)&bias[tx * 8];
    *(float4*)&bb[4] = *(const float4*)&bias[tx * 8 + 4];
    #pragma unroll
    for (int i = 0; i < 8; ++i) {
        int gr = rowBase + ty * 8 + i;
        if (gr < M) {
            long coff = (long)gr * 64 + tx * 8;
            float4 o0, o1;
            o0.x = acc[i][0] + bb[0]; o0.y = acc[i][1] + bb[1];
            o0.z = acc[i][2] + bb[2]; o0.w = acc[i][3] + bb[3];
            o1.x = acc[i][4] + bb[4]; o1.y = acc[i][5] + bb[5];
            o1.z = acc[i][6] + bb[6]; o1.w = acc[i][7] + bb[7];
            *(float4*)&C[coff]     = o0;
            *(float4*)&C[coff + 4] = o1;
        }
    }
}

// ---------------- GATv2 edge phase: one warp per dst node ------------------
// 8 lanes per head, 4 channels per lane (float4). One LDG.128 per lane per
// edge, 3-shuffle per-head reduction, scalar online softmax per lane.
__device__ __forceinline__ float leaky02(float m) {
    return fmaxf(m, 0.f) + 0.2f * fminf(m, 0.f);
}

__global__ __launch_bounds__(256)
void gat_edge_kernel(const float* __restrict__ XL, const float* __restrict__ XR,
                     const float* __restrict__ att, const float* __restrict__ We,
                     const float* __restrict__ bias, float* __restrict__ out,
                     int applyElu) {
    int gid  = blockIdx.x * blockDim.x + threadIdx.x;
    int n    = gid >> 5;
    int lane = gid & 31;
    if (n >= NN) return;

    int base = (lane >> 3) * CH + (lane & 7) * 4;   // head*32 + chan4
    float4 xr4 = *(const float4*)&XR[n * HCC + base];
    float4 at4 = *(const float4*)&att[base];
    float4 we4 = *(const float4*)&We[base];

    float mx = -CUDART_INF_F, dn = 0.f;
    float4 acc = make_float4(0.f, 0.f, 0.f, 0.f);

    int beg = g_rowptr[n], end = g_rowptr[n + 1];

    // pipelined prologue
    int2   edN = make_int2(0, 0);
    float4 xlN = make_float4(0.f, 0.f, 0.f, 0.f);
    if (beg < end) {
        edN = g_ecsr[beg];
        xlN = *(const float4*)&XL[(long)edN.x * HCC + base];
    }

    for (int e = beg; e < end; ++e) {
        int2   ed  = edN;
        float4 xl4 = xlN;
        if (e + 1 < end) {
            edN = g_ecsr[e + 1];
            xlN = *(const float4*)&XL[(long)edN.x * HCC + base];
        }
        if (ed.x == n) continue;                    // PyG removes existing self loops
        float ae = __int_as_float(ed.y);
        float p = leaky02(fmaf(ae, we4.x, xl4.x + xr4.x)) * at4.x
                + leaky02(fmaf(ae, we4.y, xl4.y + xr4.y)) * at4.y
                + leaky02(fmaf(ae, we4.z, xl4.z + xr4.z)) * at4.z
                + leaky02(fmaf(ae, we4.w, xl4.w + xr4.w)) * at4.w;
        p += __shfl_xor_sync(0xffffffffu, p, 4);
        p += __shfl_xor_sync(0xffffffffu, p, 2);
        p += __shfl_xor_sync(0xffffffffu, p, 1);
        if (p > mx) {
            float r = __expf(mx - p);               // exp(-inf)=0 first time
            dn *= r;
            acc.x *= r; acc.y *= r; acc.z *= r; acc.w *= r;
            mx = p;
        }
        float w = __expf(p - mx);
        dn += w;
        acc.x = fmaf(w, xl4.x, acc.x);
        acc.y = fmaf(w, xl4.y, acc.y);
        acc.z = fmaf(w, xl4.z, acc.z);
        acc.w = fmaf(w, xl4.w, acc.w);
    }

    // self loop (always added, edge_attr = mean of incoming non-self attrs)
    {
        int   c  = g_ascnt[n];
        float la = (c > 0) ? g_asum[n] / (float)c : 0.f;
        float4 xl4 = *(const float4*)&XL[n * HCC + base];
        float p = leaky02(fmaf(la, we4.x, xl4.x + xr4.x)) * at4.x
                + leaky02(fmaf(la, we4.y, xl4.y + xr4.y)) * at4.y
                + leaky02(fmaf(la, we4.z, xl4.z + xr4.z)) * at4.z
                + leaky02(fmaf(la, we4.w, xl4.w + xr4.w)) * at4.w;
        p += __shfl_xor_sync(0xffffffffu, p, 4);
        p += __shfl_xor_sync(0xffffffffu, p, 2);
        p += __shfl_xor_sync(0xffffffffu, p, 1);
        if (p > mx) {
            float r = __expf(mx - p);
            dn *= r;
            acc.x *= r; acc.y *= r; acc.z *= r; acc.w *= r;
            mx = p;
        }
        float w = __expf(p - mx);
        dn += w;
        acc.x = fmaf(w, xl4.x, acc.x);
        acc.y = fmaf(w, xl4.y, acc.y);
        acc.z = fmaf(w, xl4.z, acc.z);
        acc.w = fmaf(w, xl4.w, acc.w);
    }

    float4 b4 = *(const float4*)&bias[base];
    float inv = 1.f / dn;
    float4 o;
    o.x = fmaf(acc.x, inv, b4.x);
    o.y = fmaf(acc.y, inv, b4.y);
    o.z = fmaf(acc.z, inv, b4.z);
    o.w = fmaf(acc.w, inv, b4.w);
    if (applyElu) {
        o.x = (o.x > 0.f) ? o.x : (__expf(o.x) - 1.f);
        o.y = (o.y > 0.f) ? o.y : (__expf(o.y) - 1.f);
        o.z = (o.z > 0.f) ? o.z : (__expf(o.z) - 1.f);
        o.w = (o.w > 0.f) ? o.w : (__expf(o.w) - 1.f);
    }
    *(float4*)&out[n * HCC + base] = o;
}

// ---------------- launch ----------------------------------------------------
extern "C" void kernel_launch(void* const* d_in, const int* in_sizes, int n_in,
                              void* d_out, int out_size) {
    const float* x     = (const float*)d_in[0];
    const int*   ei    = (const int*)d_in[1];
    const float* eattr = (const float*)d_in[2];
    const float* Wl1 = (const float*)d_in[3];
    const float* bl1 = (const float*)d_in[4];
    const float* Wr1 = (const float*)d_in[5];
    const float* br1 = (const float*)d_in[6];
    const float* We1 = (const float*)d_in[7];
    const float* att1= (const float*)d_in[8];
    const float* b1  = (const float*)d_in[9];
    const float* Wl2 = (const float*)d_in[10];
    const float* bl2 = (const float*)d_in[11];
    const float* Wr2 = (const float*)d_in[12];
    const float* br2 = (const float*)d_in[13];
    const float* We2 = (const float*)d_in[14];
    const float* att2= (const float*)d_in[15];
    const float* b2  = (const float*)d_in[16];
    const float* Wo  = (const float*)d_in[17];
    const float* bo  = (const float*)d_in[18];
    float* out = (float*)d_out;

    int E = in_sizes[1] / 2;        // 640000
    int N = in_sizes[0] / HCC;      // 20000

    float *XL, *XR, *H;
    cudaGetSymbolAddress((void**)&XL, g_XL);
    cudaGetSymbolAddress((void**)&XR, g_XR);
    cudaGetSymbolAddress((void**)&H,  g_H);

    // secondary stream + events for CSR || GEMM1 overlap (host objects,
    // created once on the uncaptured correctness call, reused thereafter)
    static cudaStream_t s1 = nullptr;
    static cudaEvent_t evFork = nullptr, evJoin = nullptr;
    if (s1 == nullptr) {
        cudaStreamCreateWithFlags(&s1, cudaStreamNonBlocking);
        cudaEventCreateWithFlags(&evFork, cudaEventDisableTiming);
        cudaEventCreateWithFlags(&evJoin, cudaEventDisableTiming);
    }

    int dualGrid = (N + 63) / 64;       // 64-row tiles
    int outGrid  = (N + 127) / 128;     // 128-row tiles
    int edgeBlocks = (N * 32 + 255) / 256;   // one warp per node
    int eBlocks    = (E + 255) / 256;
    int nBlocks    = (N + 255) / 256;

    // ---- fork: CSR build on s1, layer-1 GEMM on main stream, join before edge
    cudaEventRecord(evFork, 0);
    cudaStreamWaitEvent(s1, evFork, 0);

    zero_counts_kernel<<<nBlocks, 256, 0, s1>>>();
    hist_kernel<<<eBlocks, 256, 0, s1>>>(ei, eattr, E);
    scan_kernel<<<1, 1024, 0, s1>>>(N);
    scatter_kernel<<<eBlocks, 256, 0, s1>>>(ei, eattr, E);
    cudaEventRecord(evJoin, s1);

    sgemm_dual_bias<<<dualGrid, 128>>>(x, Wl1, Wr1, bl1, br1, XL, XR, N);

    cudaStreamWaitEvent(0, evJoin, 0);

    // layer 1 edge phase
    gat_edge_kernel<<<edgeBlocks, 256>>>(XL, XR, att1, We1, b1, H, 1);

    // layer 2
    sgemm_dual_bias<<<dualGrid, 128>>>(H, Wl2, Wr2, bl2, br2, XL, XR, N);
    gat_edge_kernel<<<edgeBlocks, 256>>>(XL, XR, att2, We2, b2, H, 1);

    // output projection
    sgemm_out_bias<<<outGrid, 128>>>(H, Wo, bo, out, N);
}

// round 7
// speedup vs baseline: 1.1270x; 1.1270x over previous
#include <cuda_runtime.h>
#include <math_constants.h>

// Problem constants (fixed by the dataset)
#define NN   20000      // nodes
#define EE   640000     // edges
#define HCC  128        // H * C
#define NH   4          // heads
#define CH   32         // channels per head
#define DOUT 64

// ---------------- device scratch (static: no allocations allowed) -----------
__device__ float g_XL[NN * HCC];
__device__ float g_XR[NN * HCC];
__device__ float g_H [NN * HCC];
__device__ int   g_cnt[NN];
__device__ int   g_cur[NN];
__device__ float g_asum[NN];     // sum of non-self incoming edge_attr
__device__ int   g_ascnt[NN];    // count of non-self incoming edges
__device__ int   g_rowptr[NN + 1];
__device__ int2  g_ecsr[EE];     // packed (src, edge_attr bits), CSR order by dst

// ---------------- CSR build ------------------------------------------------
__global__ void zero_counts_kernel() {
    int i = blockIdx.x * blockDim.x + threadIdx.x;
    if (i < NN) { g_cnt[i] = 0; g_cur[i] = 0; g_asum[i] = 0.f; g_ascnt[i] = 0; }
}

// histogram + per-dst non-self edge_attr sum/count (for fill_value='mean')
__global__ void hist_kernel(const int* __restrict__ ei,
                            const float* __restrict__ eattr, int E) {
    int e = blockIdx.x * blockDim.x + threadIdx.x;
    if (e >= E) return;
    int s = ei[e];
    int d = ei[E + e];
    if (d < 0 || d >= NN) return;
    atomicAdd(&g_cnt[d], 1);
    if (s != d) {
        atomicAdd(&g_asum[d], eattr[e]);
        atomicAdd(&g_ascnt[d], 1);
    }
}

// single-block exclusive scan of g_cnt -> g_rowptr
__global__ void scan_kernel(int n) {
    __shared__ int sums[1024];
    int tid = threadIdx.x;
    int per = (n + 1023) >> 10;
    int beg = tid * per;
    int end = beg + per;
    if (beg > n) beg = n;
    if (end > n) end = n;
    int s = 0;
    for (int i = beg; i < end; ++i) s += g_cnt[i];
    sums[tid] = s;
    __syncthreads();
    for (int off = 1; off < 1024; off <<= 1) {
        int v = (tid >= off) ? sums[tid - off] : 0;
        __syncthreads();
        sums[tid] += v;
        __syncthreads();
    }
    int run = (tid == 0) ? 0 : sums[tid - 1];
    for (int i = beg; i < end; ++i) { g_rowptr[i] = run; run += g_cnt[i]; }
    if (tid == 0) g_rowptr[n] = sums[1023];
}

__global__ void scatter_kernel(const int* __restrict__ ei,
                               const float* __restrict__ eattr, int E) {
    int e = blockIdx.x * blockDim.x + threadIdx.x;
    if (e >= E) return;
    int dst = ei[E + e];
    if (dst < 0 || dst >= NN) return;
    int pos = g_rowptr[dst] + atomicAdd(&g_cur[dst], 1);
    g_ecsr[pos] = make_int2(ei[e], __float_as_int(eattr[e]));
}

// ---------------- pair SGEMM: grid.y selects (B, bias, C) -------------------
// Computes C = A[M,128] @ B[128,128] + bias.
// 128x128 block tile, BK=8, 256 threads, 8x8 micro (split-tile layout:
// rows {ty*4, ty*4+64}+0..3, cols {tx*4, tx*4+64}+0..3) -> conflict-free LDS.
__global__ __launch_bounds__(256)
void sgemm_pair_bias(const float* __restrict__ A,
                     const float* __restrict__ B0, const float* __restrict__ B1,
                     const float* __restrict__ c0, const float* __restrict__ c1,
                     float* __restrict__ C0, float* __restrict__ C1,
                     int M) {
    const float* B    = blockIdx.y ? B1 : B0;
    const float* bias = blockIdx.y ? c1 : c0;
    float*       C    = blockIdx.y ? C1 : C0;

    __shared__ float As[8][128];   // transposed: As[k][m]
    __shared__ float Bs[8][128];   // Bs[k][n]
    int tid = threadIdx.x;
    int tx = tid & 15;             // 16 col groups
    int ty = tid >> 4;             // 16 row groups
    int rowBase = blockIdx.x * 128;

    float acc[8][8] = {};

    // global load indices (per k0 step, one float4 of A and one of B each)
    int ar = tid >> 1;             // 0..127 row
    int ak = (tid & 1) * 4;        // 0 or 4
    int bk = tid >> 5;             // 0..7 k-row
    int bn = (tid & 31) * 4;       // 0..124 col

    for (int k0 = 0; k0 < 128; k0 += 8) {
        int gr = rowBase + ar;
        float4 av = (gr < M) ? *(const float4*)&A[(long)gr * 128 + k0 + ak]
                             : make_float4(0.f, 0.f, 0.f, 0.f);
        As[ak + 0][ar] = av.x;
        As[ak + 1][ar] = av.y;
        As[ak + 2][ar] = av.z;
        As[ak + 3][ar] = av.w;
        *(float4*)&Bs[bk][bn] = *(const float4*)&B[(long)(k0 + bk) * 128 + bn];
        __syncthreads();
        #pragma unroll
        for (int kk = 0; kk < 8; ++kk) {
            float a[8], b[8];
            *(float4*)&a[0] = *(const float4*)&As[kk][ty * 4];
            *(float4*)&a[4] = *(const float4*)&As[kk][ty * 4 + 64];
            *(float4*)&b[0] = *(const float4*)&Bs[kk][tx * 4];
            *(float4*)&b[4] = *(const float4*)&Bs[kk][tx * 4 + 64];
            #pragma unroll
            for (int i = 0; i < 8; ++i)
                #pragma unroll
                for (int j = 0; j < 8; ++j)
                    acc[i][j] = fmaf(a[i], b[j], acc[i][j]);
        }
        __syncthreads();
    }

    float bb[8];
    *(float4*)&bb[0] = *(const float4*)&bias[tx * 4];
    *(float4*)&bb[4] = *(const float4*)&bias[tx * 4 + 64];
    #pragma unroll
    for (int half = 0; half < 2; ++half) {
        #pragma unroll
        for (int i = 0; i < 4; ++i) {
            int gr = rowBase + half * 64 + ty * 4 + i;
            if (gr < M) {
                int ii = half * 4 + i;
                float4 o0, o1;
                o0.x = acc[ii][0] + bb[0]; o0.y = acc[ii][1] + bb[1];
                o0.z = acc[ii][2] + bb[2]; o0.w = acc[ii][3] + bb[3];
                o1.x = acc[ii][4] + bb[4]; o1.y = acc[ii][5] + bb[5];
                o1.z = acc[ii][6] + bb[6]; o1.w = acc[ii][7] + bb[7];
                long coff = (long)gr * 128;
                *(float4*)&C[coff + tx * 4]      = o0;
                *(float4*)&C[coff + tx * 4 + 64] = o1;
            }
        }
    }
}

// ---------------- output projection: C[M,64] = A[M,128] @ B[128,64] + bias --
// 128(M)x64(N) block tile, BK=16, 128 threads, 8x8 micro-tile.
__global__ __launch_bounds__(128)
void sgemm_out_bias(const float* __restrict__ A, const float* __restrict__ B,
                    const float* __restrict__ bias, float* __restrict__ C,
                    int M) {
    __shared__ float As[16][128];   // transposed: As[k][m]
    __shared__ float Bs[16][64];    // Bs[k][n]
    int tid = threadIdx.x;
    int tx = tid & 7;               // 8 col groups: cols {tx*4, tx*4+32}+0..3
    int ty = tid >> 3;              // 16 row groups: rows {ty*4, ty*4+64}+0..3
    int rowBase = blockIdx.x * 128;

    float acc[8][8] = {};

    for (int k0 = 0; k0 < 128; k0 += 16) {
        // A tile: 128 rows x 16 k = 512 float4, 4 per thread
        #pragma unroll
        for (int i = 0; i < 4; ++i) {
            int idx = tid * 4 + i;          // 0..511
            int r   = idx >> 2;             // 0..127
            int kq  = (idx & 3) * 4;
            int gr  = rowBase + r;
            float4 av = (gr < M) ? *(const float4*)&A[(long)gr * 128 + k0 + kq]
                                 : make_float4(0.f, 0.f, 0.f, 0.f);
            As[kq + 0][r] = av.x;
            As[kq + 1][r] = av.y;
            As[kq + 2][r] = av.z;
            As[kq + 3][r] = av.w;
        }
        // B tile: 16 k x 64 n = 256 float4, 2 per thread
        #pragma unroll
        for (int i = 0; i < 2; ++i) {
            int idx = i * 128 + tid;        // 0..255
            int kr  = idx >> 4;             // 0..15
            int nc  = (idx & 15) * 4;       // 0..60
            *(float4*)&Bs[kr][nc] = *(const float4*)&B[(long)(k0 + kr) * 64 + nc];
        }
        __syncthreads();
        #pragma unroll
        for (int kk = 0; kk < 16; ++kk) {
            float a[8], b[8];
            *(float4*)&a[0] = *(const float4*)&As[kk][ty * 4];
            *(float4*)&a[4] = *(const float4*)&As[kk][ty * 4 + 64];
            *(float4*)&b[0] = *(const float4*)&Bs[kk][tx * 4];
            *(float4*)&b[4] = *(const float4*)&Bs[kk][tx * 4 + 32];
            #pragma unroll
            for (int i = 0; i < 8; ++i)
                #pragma unroll
                for (int j = 0; j < 8; ++j)
                    acc[i][j] = fmaf(a[i], b[j], acc[i][j]);
        }
        __syncthreads();
    }

    float bb[8];
    *(float4*)&bb[0] = *(const float4*)&bias[tx * 4];
    *(float4*)&bb[4] = *(const float4*)&bias[tx * 4 + 32];
    #pragma unroll
    for (int half = 0; half < 2; ++half) {
        #pragma unroll
        for (int i = 0; i < 4; ++i) {
            int gr = rowBase + half * 64 + ty * 4 + i;
            if (gr < M) {
                int ii = half * 4 + i;
                float4 o0, o1;
                o0.x = acc[ii][0] + bb[0]; o0.y = acc[ii][1] + bb[1];
                o0.z = acc[ii][2] + bb[2]; o0.w = acc[ii][3] + bb[3];
                o1.x = acc[ii][4] + bb[4]; o1.y = acc[ii][5] + bb[5];
                o1.z = acc[ii][6] + bb[6]; o1.w = acc[ii][7] + bb[7];
                long coff = (long)gr * 64;
                *(float4*)&C[coff + tx * 4]      = o0;
                *(float4*)&C[coff + tx * 4 + 32] = o1;
            }
        }
    }
}

// ---------------- GATv2 edge phase: one warp per dst node ------------------
// 8 lanes per head, 4 channels per lane (float4). One LDG.128 per lane per
// edge, 3-shuffle per-head reduction, scalar online softmax per lane.
__device__ __forceinline__ float leaky02(float m) {
    return fmaxf(m, 0.f) + 0.2f * fminf(m, 0.f);
}

__global__ __launch_bounds__(256)
void gat_edge_kernel(const float* __restrict__ XL, const float* __restrict__ XR,
                     const float* __restrict__ att, const float* __restrict__ We,
                     const float* __restrict__ bias, float* __restrict__ out,
                     int applyElu) {
    int gid  = blockIdx.x * blockDim.x + threadIdx.x;
    int n    = gid >> 5;
    int lane = gid & 31;
    if (n >= NN) return;

    int base = (lane >> 3) * CH + (lane & 7) * 4;   // head*32 + chan4
    float4 xr4 = *(const float4*)&XR[n * HCC + base];
    float4 at4 = *(const float4*)&att[base];
    float4 we4 = *(const float4*)&We[base];

    float mx = -CUDART_INF_F, dn = 0.f;
    float4 acc = make_float4(0.f, 0.f, 0.f, 0.f);

    int beg = g_rowptr[n], end = g_rowptr[n + 1];

    // pipelined prologue
    int2   edN = make_int2(0, 0);
    float4 xlN = make_float4(0.f, 0.f, 0.f, 0.f);
    if (beg < end) {
        edN = g_ecsr[beg];
        xlN = *(const float4*)&XL[(long)edN.x * HCC + base];
    }

    for (int e = beg; e < end; ++e) {
        int2   ed  = edN;
        float4 xl4 = xlN;
        if (e + 1 < end) {
            edN = g_ecsr[e + 1];
            xlN = *(const float4*)&XL[(long)edN.x * HCC + base];
        }
        if (ed.x == n) continue;                    // PyG removes existing self loops
        float ae = __int_as_float(ed.y);
        float p = leaky02(fmaf(ae, we4.x, xl4.x + xr4.x)) * at4.x
                + leaky02(fmaf(ae, we4.y, xl4.y + xr4.y)) * at4.y
                + leaky02(fmaf(ae, we4.z, xl4.z + xr4.z)) * at4.z
                + leaky02(fmaf(ae, we4.w, xl4.w + xr4.w)) * at4.w;
        p += __shfl_xor_sync(0xffffffffu, p, 4);
        p += __shfl_xor_sync(0xffffffffu, p, 2);
        p += __shfl_xor_sync(0xffffffffu, p, 1);
        if (p > mx) {
            float r = __expf(mx - p);               // exp(-inf)=0 first time
            dn *= r;
            acc.x *= r; acc.y *= r; acc.z *= r; acc.w *= r;
            mx = p;
        }
        float w = __expf(p - mx);
        dn += w;
        acc.x = fmaf(w, xl4.x, acc.x);
        acc.y = fmaf(w, xl4.y, acc.y);
        acc.z = fmaf(w, xl4.z, acc.z);
        acc.w = fmaf(w, xl4.w, acc.w);
    }

    // self loop (always added, edge_attr = mean of incoming non-self attrs)
    {
        int   c  = g_ascnt[n];
        float la = (c > 0) ? g_asum[n] / (float)c : 0.f;
        float4 xl4 = *(const float4*)&XL[n * HCC + base];
        float p = leaky02(fmaf(la, we4.x, xl4.x + xr4.x)) * at4.x
                + leaky02(fmaf(la, we4.y, xl4.y + xr4.y)) * at4.y
                + leaky02(fmaf(la, we4.z, xl4.z + xr4.z)) * at4.z
                + leaky02(fmaf(la, we4.w, xl4.w + xr4.w)) * at4.w;
        p += __shfl_xor_sync(0xffffffffu, p, 4);
        p += __shfl_xor_sync(0xffffffffu, p, 2);
        p += __shfl_xor_sync(0xffffffffu, p, 1);
        if (p > mx) {
            float r = __expf(mx - p);
            dn *= r;
            acc.x *= r; acc.y *= r; acc.z *= r; acc.w *= r;
            mx = p;
        }
        float w = __expf(p - mx);
        dn += w;
        acc.x = fmaf(w, xl4.x, acc.x);
        acc.y = fmaf(w, xl4.y, acc.y);
        acc.z = fmaf(w, xl4.z, acc.z);
        acc.w = fmaf(w, xl4.w, acc.w);
    }

    float4 b4 = *(const float4*)&bias[base];
    float inv = 1.f / dn;
    float4 o;
    o.x = fmaf(acc.x, inv, b4.x);
    o.y = fmaf(acc.y, inv, b4.y);
    o.z = fmaf(acc.z, inv, b4.z);
    o.w = fmaf(acc.w, inv, b4.w);
    if (applyElu) {
        o.x = (o.x > 0.f) ? o.x : (__expf(o.x) - 1.f);
        o.y = (o.y > 0.f) ? o.y : (__expf(o.y) - 1.f);
        o.z = (o.z > 0.f) ? o.z : (__expf(o.z) - 1.f);
        o.w = (o.w > 0.f) ? o.w : (__expf(o.w) - 1.f);
    }
    *(float4*)&out[n * HCC + base] = o;
}

// ---------------- launch ----------------------------------------------------
extern "C" void kernel_launch(void* const* d_in, const int* in_sizes, int n_in,
                              void* d_out, int out_size) {
    const float* x     = (const float*)d_in[0];
    const int*   ei    = (const int*)d_in[1];
    const float* eattr = (const float*)d_in[2];
    const float* Wl1 = (const float*)d_in[3];
    const float* bl1 = (const float*)d_in[4];
    const float* Wr1 = (const float*)d_in[5];
    const float* br1 = (const float*)d_in[6];
    const float* We1 = (const float*)d_in[7];
    const float* att1= (const float*)d_in[8];
    const float* b1  = (const float*)d_in[9];
    const float* Wl2 = (const float*)d_in[10];
    const float* bl2 = (const float*)d_in[11];
    const float* Wr2 = (const float*)d_in[12];
    const float* br2 = (const float*)d_in[13];
    const float* We2 = (const float*)d_in[14];
    const float* att2= (const float*)d_in[15];
    const float* b2  = (const float*)d_in[16];
    const float* Wo  = (const float*)d_in[17];
    const float* bo  = (const float*)d_in[18];
    float* out = (float*)d_out;

    int E = in_sizes[1] / 2;        // 640000
    int N = in_sizes[0] / HCC;      // 20000

    float *XL, *XR, *H;
    cudaGetSymbolAddress((void**)&XL, g_XL);
    cudaGetSymbolAddress((void**)&XR, g_XR);
    cudaGetSymbolAddress((void**)&H,  g_H);

    // secondary stream + events for CSR || GEMM1 overlap (host objects,
    // created once on the uncaptured correctness call, reused thereafter)
    static cudaStream_t s1 = nullptr;
    static cudaEvent_t evFork = nullptr, evJoin = nullptr;
    if (s1 == nullptr) {
        cudaStreamCreateWithFlags(&s1, cudaStreamNonBlocking);
        cudaEventCreateWithFlags(&evFork, cudaEventDisableTiming);
        cudaEventCreateWithFlags(&evJoin, cudaEventDisableTiming);
    }

    dim3 pairGrid((N + 127) / 128, 2);  // grid.y: 0 -> (Wl, CL), 1 -> (Wr, CR)
    int outGrid  = (N + 127) / 128;
    int edgeBlocks = (N * 32 + 255) / 256;   // one warp per node
    int eBlocks    = (E + 255) / 256;
    int nBlocks    = (N + 255) / 256;

    // ---- fork: CSR build on s1, layer-1 GEMM on main stream, join before edge
    cudaEventRecord(evFork, 0);
    cudaStreamWaitEvent(s1, evFork, 0);

    zero_counts_kernel<<<nBlocks, 256, 0, s1>>>();
    hist_kernel<<<eBlocks, 256, 0, s1>>>(ei, eattr, E);
    scan_kernel<<<1, 1024, 0, s1>>>(N);
    scatter_kernel<<<eBlocks, 256, 0, s1>>>(ei, eattr, E);
    cudaEventRecord(evJoin, s1);

    sgemm_pair_bias<<<pairGrid, 256>>>(x, Wl1, Wr1, bl1, br1, XL, XR, N);

    cudaStreamWaitEvent(0, evJoin, 0);

    // layer 1 edge phase
    gat_edge_kernel<<<edgeBlocks, 256>>>(XL, XR, att1, We1, b1, H, 1);

    // layer 2
    sgemm_pair_bias<<<pairGrid, 256>>>(H, Wl2, Wr2, bl2, br2, XL, XR, N);
    gat_edge_kernel<<<edgeBlocks, 256>>>(XL, XR, att2, We2, b2, H, 1);

    // output projection
    sgemm_out_bias<<<outGrid, 128>>>(H, Wo, bo, out, N);
}

// round 9
// speedup vs baseline: 1.1870x; 1.0532x over previous
#include <cuda_runtime.h>
#include <math_constants.h>

// Problem constants (fixed by the dataset)
#define NN   20000      // nodes
#define EE   640000     // edges
#define HCC  128        // H * C
#define NH   4          // heads
#define CH   32         // channels per head
#define DOUT 64

// ---------------- device scratch (static: no allocations allowed) -----------
__device__ float g_XL[NN * HCC];
__device__ float g_XR[NN * HCC];
__device__ float g_H [NN * HCC];
__device__ int   g_cnt[NN];
__device__ int   g_cur[NN];
__device__ float g_asum[NN];     // sum of non-self incoming edge_attr
__device__ int   g_ascnt[NN];    // count of non-self incoming edges
__device__ int   g_rowptr[NN + 1];
__device__ int2  g_ecsr[EE];     // packed (src, edge_attr bits), CSR order by dst

// ---------------- packed fp32x2 helpers (Blackwell FFMA2 via PTX) -----------
__device__ __forceinline__ void ffma2(unsigned long long& d,
                                      unsigned long long a,
                                      unsigned long long b) {
    asm("fma.rn.f32x2 %0, %1, %2, %0;" : "+l"(d) : "l"(a), "l"(b));
}
__device__ __forceinline__ unsigned long long pack2(float x) {
    unsigned long long r;
    asm("mov.b64 %0, {%1, %1};" : "=l"(r) : "f"(x));
    return r;
}
__device__ __forceinline__ float2 unpack2(unsigned long long v) {
    float2 o;
    asm("mov.b64 {%0, %1}, %2;" : "=f"(o.x), "=f"(o.y) : "l"(v));
    return o;
}

// ---------------- CSR build ------------------------------------------------
__global__ void zero_counts_kernel() {
    int i = blockIdx.x * blockDim.x + threadIdx.x;
    if (i < NN) { g_cnt[i] = 0; g_cur[i] = 0; g_asum[i] = 0.f; g_ascnt[i] = 0; }
}

// histogram + per-dst non-self edge_attr sum/count (for fill_value='mean')
__global__ void hist_kernel(const int* __restrict__ ei,
                            const float* __restrict__ eattr, int E) {
    int e = blockIdx.x * blockDim.x + threadIdx.x;
    if (e >= E) return;
    int s = ei[e];
    int d = ei[E + e];
    if (d < 0 || d >= NN) return;
    atomicAdd(&g_cnt[d], 1);
    if (s != d) {
        atomicAdd(&g_asum[d], eattr[e]);
        atomicAdd(&g_ascnt[d], 1);
    }
}

// single-block exclusive scan of g_cnt -> g_rowptr
__global__ void scan_kernel(int n) {
    __shared__ int sums[1024];
    int tid = threadIdx.x;
    int per = (n + 1023) >> 10;
    int beg = tid * per;
    int end = beg + per;
    if (beg > n) beg = n;
    if (end > n) end = n;
    int s = 0;
    for (int i = beg; i < end; ++i) s += g_cnt[i];
    sums[tid] = s;
    __syncthreads();
    for (int off = 1; off < 1024; off <<= 1) {
        int v = (tid >= off) ? sums[tid - off] : 0;
        __syncthreads();
        sums[tid] += v;
        __syncthreads();
    }
    int run = (tid == 0) ? 0 : sums[tid - 1];
    for (int i = beg; i < end; ++i) { g_rowptr[i] = run; run += g_cnt[i]; }
    if (tid == 0) g_rowptr[n] = sums[1023];
}

__global__ void scatter_kernel(const int* __restrict__ ei,
                               const float* __restrict__ eattr, int E) {
    int e = blockIdx.x * blockDim.x + threadIdx.x;
    if (e >= E) return;
    int dst = ei[E + e];
    if (dst < 0 || dst >= NN) return;
    int pos = g_rowptr[dst] + atomicAdd(&g_cur[dst], 1);
    g_ecsr[pos] = make_int2(ei[e], __float_as_int(eattr[e]));
}

// ---------------- fused dual SGEMM: CL = A@Bl + bl, CR = A@Br + br ---------
// 64x64 tiles, BK=16, 256 threads, 4x4 per thread per output, shared A tile.
// Inner product uses packed fma.rn.f32x2 (FFMA2): halves FMA issue count.
__global__ __launch_bounds__(256)
void sgemm_dual_bias(const float* __restrict__ A,
                     const float* __restrict__ Bl, const float* __restrict__ Br,
                     const float* __restrict__ bl, const float* __restrict__ br,
                     float* __restrict__ CL, float* __restrict__ CR,
                     int M, int N, int K) {
    __shared__ float As [16][64];  // transposed: As[k][m]
    __shared__ float Bls[16][64];  // Bls[k][n]
    __shared__ float Brs[16][64];
    int tid = threadIdx.x;
    int tx = tid & 15, ty = tid >> 4;
    int bm = blockIdx.x, bn = blockIdx.y;
    int rowBase = bm * 64;

    int aRow = tid >> 2;          // 0..63
    int aK   = (tid & 3) * 4;     // 0,4,8,12
    int bK   = tid >> 4;          // 0..15
    int bN   = (tid & 15) * 4;    // 0..60

    unsigned long long accL[4][2] = {};   // each holds 2 packed fp32 cols
    unsigned long long accR[4][2] = {};

    for (int k0 = 0; k0 < K; k0 += 16) {
        float4 av;
        int gr = rowBase + aRow;
        if (gr < M) av = *(const float4*)&A[(long)gr * K + k0 + aK];
        else        av = make_float4(0.f, 0.f, 0.f, 0.f);
        As[aK + 0][aRow] = av.x;
        As[aK + 1][aRow] = av.y;
        As[aK + 2][aRow] = av.z;
        As[aK + 3][aRow] = av.w;
        long boff = (long)(k0 + bK) * N + bn * 64 + bN;
        *(float4*)&Bls[bK][bN] = *(const float4*)&Bl[boff];
        *(float4*)&Brs[bK][bN] = *(const float4*)&Br[boff];
        __syncthreads();
        #pragma unroll
        for (int kk = 0; kk < 16; ++kk) {
            float4 a4 = *(const float4*)&As[kk][ty * 4];
            ulonglong2 blp = *(const ulonglong2*)&Bls[kk][tx * 4];
            ulonglong2 brp = *(const ulonglong2*)&Brs[kk][tx * 4];
            unsigned long long ap[4];
            ap[0] = pack2(a4.x); ap[1] = pack2(a4.y);
            ap[2] = pack2(a4.z); ap[3] = pack2(a4.w);
            #pragma unroll
            for (int i = 0; i < 4; ++i) {
                ffma2(accL[i][0], ap[i], blp.x);
                ffma2(accL[i][1], ap[i], blp.y);
                ffma2(accR[i][0], ap[i], brp.x);
                ffma2(accR[i][1], ap[i], brp.y);
            }
        }
        __syncthreads();
    }
    float4 bl4 = *(const float4*)&bl[bn * 64 + tx * 4];
    float4 br4 = *(const float4*)&br[bn * 64 + tx * 4];
    #pragma unroll
    for (int i = 0; i < 4; ++i) {
        int gr = rowBase + ty * 4 + i;
        if (gr < M) {
            float2 l0 = unpack2(accL[i][0]);
            float2 l1 = unpack2(accL[i][1]);
            float2 r0 = unpack2(accR[i][0]);
            float2 r1 = unpack2(accR[i][1]);
            float4 ol, orr;
            ol.x  = l0.x + bl4.x; ol.y  = l0.y + bl4.y;
            ol.z  = l1.x + bl4.z; ol.w  = l1.y + bl4.w;
            orr.x = r0.x + br4.x; orr.y = r0.y + br4.y;
            orr.z = r1.x + br4.z; orr.w = r1.y + br4.w;
            long coff = (long)gr * N + bn * 64 + tx * 4;
            *(float4*)&CL[coff] = ol;
            *(float4*)&CR[coff] = orr;
        }
    }
}

// ---------------- single SGEMM (output projection), FFMA2 inner -------------
__global__ __launch_bounds__(256)
void sgemm_bias(const float* __restrict__ A, const float* __restrict__ B,
                const float* __restrict__ bias, float* __restrict__ C,
                int M, int N, int K) {
    __shared__ float As[16][64];
    __shared__ float Bs[16][64];
    int tid = threadIdx.x;
    int tx = tid & 15, ty = tid >> 4;
    int bm = blockIdx.x, bn = blockIdx.y;
    int rowBase = bm * 64;

    int aRow = tid >> 2;
    int aK   = (tid & 3) * 4;
    int bK   = tid >> 4;
    int bN   = (tid & 15) * 4;

    unsigned long long acc[4][2] = {};
    for (int k0 = 0; k0 < K; k0 += 16) {
        float4 av;
        int gr = rowBase + aRow;
        if (gr < M) av = *(const float4*)&A[(long)gr * K + k0 + aK];
        else        av = make_float4(0.f, 0.f, 0.f, 0.f);
        As[aK + 0][aRow] = av.x;
        As[aK + 1][aRow] = av.y;
        As[aK + 2][aRow] = av.z;
        As[aK + 3][aRow] = av.w;
        *(float4*)&Bs[bK][bN] = *(const float4*)&B[(long)(k0 + bK) * N + bn * 64 + bN];
        __syncthreads();
        #pragma unroll
        for (int kk = 0; kk < 16; ++kk) {
            float4 a4 = *(const float4*)&As[kk][ty * 4];
            ulonglong2 bp = *(const ulonglong2*)&Bs[kk][tx * 4];
            unsigned long long ap[4];
            ap[0] = pack2(a4.x); ap[1] = pack2(a4.y);
            ap[2] = pack2(a4.z); ap[3] = pack2(a4.w);
            #pragma unroll
            for (int i = 0; i < 4; ++i) {
                ffma2(acc[i][0], ap[i], bp.x);
                ffma2(acc[i][1], ap[i], bp.y);
            }
        }
        __syncthreads();
    }
    float4 bias4 = *(const float4*)&bias[bn * 64 + tx * 4];
    #pragma unroll
    for (int i = 0; i < 4; ++i) {
        int gr = rowBase + ty * 4 + i;
        if (gr < M) {
            float2 c0 = unpack2(acc[i][0]);
            float2 c1 = unpack2(acc[i][1]);
            float4 o;
            o.x = c0.x + bias4.x;
            o.y = c0.y + bias4.y;
            o.z = c1.x + bias4.z;
            o.w = c1.y + bias4.w;
            *(float4*)&C[(long)gr * N + bn * 64 + tx * 4] = o;
        }
    }
}

// ---------------- GATv2 edge phase: one warp per dst node ------------------
// 8 lanes per head, 4 channels per lane (float4). One LDG.128 per lane per
// edge, 3-shuffle per-head reduction, scalar online softmax per lane.
__device__ __forceinline__ float leaky02(float m) {
    return fmaxf(m, 0.f) + 0.2f * fminf(m, 0.f);
}

__global__ __launch_bounds__(256)
void gat_edge_kernel(const float* __restrict__ XL, const float* __restrict__ XR,
                     const float* __restrict__ att, const float* __restrict__ We,
                     const float* __restrict__ bias, float* __restrict__ out,
                     int applyElu) {
    int gid  = blockIdx.x * blockDim.x + threadIdx.x;
    int n    = gid >> 5;
    int lane = gid & 31;
    if (n >= NN) return;

    int base = (lane >> 3) * CH + (lane & 7) * 4;   // head*32 + chan4
    float4 xr4 = *(const float4*)&XR[n * HCC + base];
    float4 at4 = *(const float4*)&att[base];
    float4 we4 = *(const float4*)&We[base];

    float mx = -CUDART_INF_F, dn = 0.f;
    float4 acc = make_float4(0.f, 0.f, 0.f, 0.f);

    int beg = g_rowptr[n], end = g_rowptr[n + 1];

    // pipelined prologue
    int2   edN = make_int2(0, 0);
    float4 xlN = make_float4(0.f, 0.f, 0.f, 0.f);
    if (beg < end) {
        edN = g_ecsr[beg];
        xlN = *(const float4*)&XL[(long)edN.x * HCC + base];
    }

    for (int e = beg; e < end; ++e) {
        int2   ed  = edN;
        float4 xl4 = xlN;
        if (e + 1 < end) {
            edN = g_ecsr[e + 1];
            xlN = *(const float4*)&XL[(long)edN.x * HCC + base];
        }
        if (ed.x == n) continue;                    // PyG removes existing self loops
        float ae = __int_as_float(ed.y);
        float p = leaky02(fmaf(ae, we4.x, xl4.x + xr4.x)) * at4.x
                + leaky02(fmaf(ae, we4.y, xl4.y + xr4.y)) * at4.y
                + leaky02(fmaf(ae, we4.z, xl4.z + xr4.z)) * at4.z
                + leaky02(fmaf(ae, we4.w, xl4.w + xr4.w)) * at4.w;
        p += __shfl_xor_sync(0xffffffffu, p, 4);
        p += __shfl_xor_sync(0xffffffffu, p, 2);
        p += __shfl_xor_sync(0xffffffffu, p, 1);
        if (p > mx) {
            float r = __expf(mx - p);               // exp(-inf)=0 first time
            dn *= r;
            acc.x *= r; acc.y *= r; acc.z *= r; acc.w *= r;
            mx = p;
        }
        float w = __expf(p - mx);
        dn += w;
        acc.x = fmaf(w, xl4.x, acc.x);
        acc.y = fmaf(w, xl4.y, acc.y);
        acc.z = fmaf(w, xl4.z, acc.z);
        acc.w = fmaf(w, xl4.w, acc.w);
    }

    // self loop (always added, edge_attr = mean of incoming non-self attrs)
    {
        int   c  = g_ascnt[n];
        float la = (c > 0) ? g_asum[n] / (float)c : 0.f;
        float4 xl4 = *(const float4*)&XL[n * HCC + base];
        float p = leaky02(fmaf(la, we4.x, xl4.x + xr4.x)) * at4.x
                + leaky02(fmaf(la, we4.y, xl4.y + xr4.y)) * at4.y
                + leaky02(fmaf(la, we4.z, xl4.z + xr4.z)) * at4.z
                + leaky02(fmaf(la, we4.w, xl4.w + xr4.w)) * at4.w;
        p += __shfl_xor_sync(0xffffffffu, p, 4);
        p += __shfl_xor_sync(0xffffffffu, p, 2);
        p += __shfl_xor_sync(0xffffffffu, p, 1);
        if (p > mx) {
            float r = __expf(mx - p);
            dn *= r;
            acc.x *= r; acc.y *= r; acc.z *= r; acc.w *= r;
            mx = p;
        }
        float w = __expf(p - mx);
        dn += w;
        acc.x = fmaf(w, xl4.x, acc.x);
        acc.y = fmaf(w, xl4.y, acc.y);
        acc.z = fmaf(w, xl4.z, acc.z);
        acc.w = fmaf(w, xl4.w, acc.w);
    }

    float4 b4 = *(const float4*)&bias[base];
    float inv = 1.f / dn;
    float4 o;
    o.x = fmaf(acc.x, inv, b4.x);
    o.y = fmaf(acc.y, inv, b4.y);
    o.z = fmaf(acc.z, inv, b4.z);
    o.w = fmaf(acc.w, inv, b4.w);
    if (applyElu) {
        o.x = (o.x > 0.f) ? o.x : (__expf(o.x) - 1.f);
        o.y = (o.y > 0.f) ? o.y : (__expf(o.y) - 1.f);
        o.z = (o.z > 0.f) ? o.z : (__expf(o.z) - 1.f);
        o.w = (o.w > 0.f) ? o.w : (__expf(o.w) - 1.f);
    }
    *(float4*)&out[n * HCC + base] = o;
}

// ---------------- launch ----------------------------------------------------
extern "C" void kernel_launch(void* const* d_in, const int* in_sizes, int n_in,
                              void* d_out, int out_size) {
    const float* x     = (const float*)d_in[0];
    const int*   ei    = (const int*)d_in[1];
    const float* eattr = (const float*)d_in[2];
    const float* Wl1 = (const float*)d_in[3];
    const float* bl1 = (const float*)d_in[4];
    const float* Wr1 = (const float*)d_in[5];
    const float* br1 = (const float*)d_in[6];
    const float* We1 = (const float*)d_in[7];
    const float* att1= (const float*)d_in[8];
    const float* b1  = (const float*)d_in[9];
    const float* Wl2 = (const float*)d_in[10];
    const float* bl2 = (const float*)d_in[11];
    const float* Wr2 = (const float*)d_in[12];
    const float* br2 = (const float*)d_in[13];
    const float* We2 = (const float*)d_in[14];
    const float* att2= (const float*)d_in[15];
    const float* b2  = (const float*)d_in[16];
    const float* Wo  = (const float*)d_in[17];
    const float* bo  = (const float*)d_in[18];
    float* out = (float*)d_out;

    int E = in_sizes[1] / 2;        // 640000
    int N = in_sizes[0] / HCC;      // 20000

    float *XL, *XR, *H;
    cudaGetSymbolAddress((void**)&XL, g_XL);
    cudaGetSymbolAddress((void**)&XR, g_XR);
    cudaGetSymbolAddress((void**)&H,  g_H);

    // secondary stream + events for CSR || GEMM1 overlap (host objects,
    // created once on the uncaptured correctness call, reused thereafter)
    static cudaStream_t s1 = nullptr;
    static cudaEvent_t evFork = nullptr, evJoin = nullptr;
    if (s1 == nullptr) {
        cudaStreamCreateWithFlags(&s1, cudaStreamNonBlocking);
        cudaEventCreateWithFlags(&evFork, cudaEventDisableTiming);
        cudaEventCreateWithFlags(&evJoin, cudaEventDisableTiming);
    }

    dim3 gemmGrid((N + 63) / 64, HCC / 64);
    dim3 gemmGridOut((N + 63) / 64, DOUT / 64);
    int edgeBlocks = (N * 32 + 255) / 256;   // one warp per node
    int eBlocks    = (E + 255) / 256;
    int nBlocks    = (N + 255) / 256;

    // ---- fork: CSR build on s1, layer-1 GEMM on main stream, join before edge
    cudaEventRecord(evFork, 0);
    cudaStreamWaitEvent(s1, evFork, 0);

    zero_counts_kernel<<<nBlocks, 256, 0, s1>>>();
    hist_kernel<<<eBlocks, 256, 0, s1>>>(ei, eattr, E);
    scan_kernel<<<1, 1024, 0, s1>>>(N);
    scatter_kernel<<<eBlocks, 256, 0, s1>>>(ei, eattr, E);
    cudaEventRecord(evJoin, s1);

    sgemm_dual_bias<<<gemmGrid, 256>>>(x, Wl1, Wr1, bl1, br1, XL, XR, N, HCC, HCC);

    cudaStreamWaitEvent(0, evJoin, 0);

    // layer 1 edge phase
    gat_edge_kernel<<<edgeBlocks, 256>>>(XL, XR, att1, We1, b1, H, 1);

    // layer 2
    sgemm_dual_bias<<<gemmGrid, 256>>>(H, Wl2, Wr2, bl2, br2, XL, XR, N, HCC, HCC);
    gat_edge_kernel<<<edgeBlocks, 256>>>(XL, XR, att2, We2, b2, H, 1);

    // output projection
    sgemm_bias<<<gemmGridOut, 256>>>(H, Wo, bo, out, N, DOUT, HCC);
}